// round 7
// baseline (speedup 1.0000x reference)
#include <cuda_runtime.h>
#include <stdint.h>

// B=8, T=8, C=1024, F=4, N=8192
#define TT 8
#define BB 8
#define CC 1024
#define FF 4
#define NN (TT*CC)
#define TB 64                   // (t,b) pairs
#define SW 16                   // strip width (columns staged in smem)
#define JQ 16                   // column units per (t,b)
#define UNITS (TB*JQ)           // 1024 CTAs
#define STRIPS 4                // 64 cols per unit / SW
#define NTHREADS 512
#define KITER 8                 // 1024 rows / 128 row-groups
#define RSTRIDE 20              // num row stride in floats: (5i+g)%8 conflict-free
#define SMEM_BYTES ((CC*RSTRIDE + SW*FF + SW)*4)   // 82240 B -> 2 CTAs/SM

// per-unit partial results [unit][i][f] : 16 MB scratch
__device__ float g_partial[(size_t)UNITS * CC * FF];
// opaque 1 so ptxas keeps mad.lo as IMAD (fma pipe)
__device__ uint32_t g_one = 1u;

__device__ __forceinline__ uint32_t tf_rotl(uint32_t x, int d) {
    return __funnelshift_l(x, x, d);
}
__device__ __forceinline__ uint32_t addf(uint32_t a, uint32_t one, uint32_t b) {
    uint32_t d;
    asm("mad.lo.u32 %0, %1, %2, %3;" : "=r"(d) : "r"(a), "r"(one), "r"(b));
    return d;
}

// JAX threefry2x32 partitionable: key=(0,42), counter=(0,e), out = x0^x1.
// Takes y = e + 42 (key pre-injected); round 1 simplified since x0 starts 0.
__device__ __forceinline__ uint32_t threefry_bits(uint32_t y, uint32_t one) {
    const uint32_t K1 = 42u;
    const uint32_t K2 = 0x1BD11BDAu ^ 42u;
    uint32_t x0 = y;                       // round 1: x0 = 0 + x1
    uint32_t x1 = tf_rotl(y, 13) ^ y;
#define TF_R(d) { x0 = addf(x0, one, x1); x1 = tf_rotl(x1,(d)) ^ x0; }
    TF_R(15) TF_R(26) TF_R(6)
    x0 = addf(x0,one,K1); x1 = addf(x1,one,K2+1u);
    TF_R(17) TF_R(29) TF_R(16) TF_R(24)
    x0 = addf(x0,one,K2); x1 = addf(x1,one,2u);
    TF_R(13) TF_R(15) TF_R(26) TF_R(6)
                          x1 = addf(x1,one,K1+3u);
    TF_R(17) TF_R(29) TF_R(16) TF_R(24)
    x0 = addf(x0,one,K1); x1 = addf(x1,one,K2+4u);
    TF_R(13) TF_R(15) TF_R(26) TF_R(6)
    x0 = addf(x0,one,K2); x1 = addf(x1,one,5u);
#undef TF_R
    return x0 ^ x1;
}

__device__ __forceinline__ float ex2_fast(float a) {
    float r;
    asm("ex2.approx.ftz.f32 %0, %1;" : "=f"(r) : "f"(a));
    return r;
}

// num = exp(w+g) up to the softmax-invariant scale: ex2(w*log2e - log2(-ln u)).
// -ln u: exact v=1-u (Sterbenz) + 3-term series near u=1, MUFU lg2 elsewhere.
__device__ __forceinline__ float numerator(float ww, uint32_t bits) {
    const uint32_t ub = __umulhi(bits, 1u << 23) + 0x3f800000u;
    const float f = __uint_as_float(ub) - 1.0f;
    const float u = fmaxf(f, 1.17549435e-38f);
    const float v = 1.0f - u;
    const float poly = fmaf(v * v, fmaf(v, 0.33333333f, 0.5f), v);
    const float l2u = __log2f(u);
    const float p = (v <= 0.015625f) ? poly : (l2u * -0.69314718f);
    return ex2_fast(fmaf(ww, 1.44269504f, -__log2f(p)));
}

// One unit = (tb, jq): 64 columns x 1024 rows of one (t,b) weight matrix.
// Thread owns 4 consecutive columns: LDG.128 w, STS.128 num (row-major).
__global__ __launch_bounds__(NTHREADS, 2)
void fused_retina_kernel(const float* __restrict__ x,
                         const float* __restrict__ w) {
    const int unit = blockIdx.x;
    const int tb = unit >> 4;
    const int jq = unit & (JQ - 1);
    const int t  = tb >> 3;
    const int b  = tb & 7;
    const int jbase = jq * (STRIPS * SW);

    extern __shared__ float smem[];
    float* num  = smem;                     // [CC][RSTRIDE] row-major
    float* sxs  = smem + CC * RSTRIDE;      // [SW][FF]
    float* csum = sxs + SW * FF;            // [SW]

    const int tid = threadIdx.x;
    const int q   = tid & 3;                // column quad
    const int rr  = tid >> 2;               // 0..127 row group
    const uint32_t one = g_one;

    float acc0[FF] = {0.f,0.f,0.f,0.f};     // row i0 = tid
    float acc1[FF] = {0.f,0.f,0.f,0.f};     // row i1 = tid + 512

    for (int s = 0; s < STRIPS; ++s) {
        const int j0 = jbase + s * SW;
        if (tid < SW) csum[tid] = 0.f;
        __syncthreads();

        // ---- phase 1: hash + numerator + column partial sums ----
        const int jcol = j0 + 4 * q;
        const float* wp = w + ((size_t)tb << 20) + ((size_t)rr << 10) + jcol;
        const uint32_t pe1 = (((uint32_t)tb << 20) | ((uint32_t)rr << 10) |
                              (uint32_t)jcol) + 42u;
        float ac0 = 0.f, ac1 = 0.f, ac2 = 0.f, ac3 = 0.f;
        #pragma unroll 2
        for (int k = 0; k < KITER; ++k) {
            const int i = (k << 7) + rr;
            const float4 w4 = *reinterpret_cast<const float4*>(
                wp + ((size_t)k << 17));
            const uint32_t e1 = pe1 + ((uint32_t)k << 17);
            const float n0 = numerator(w4.x, threefry_bits(e1,      one));
            const float n1 = numerator(w4.y, threefry_bits(e1 + 1u, one));
            const float n2 = numerator(w4.z, threefry_bits(e1 + 2u, one));
            const float n3 = numerator(w4.w, threefry_bits(e1 + 3u, one));
            *reinterpret_cast<float4*>(&num[i * RSTRIDE + 4 * q]) =
                make_float4(n0, n1, n2, n3);
            ac0 += n0; ac1 += n1; ac2 += n2; ac3 += n3;
        }
        atomicAdd(&csum[4*q + 0], ac0);
        atomicAdd(&csum[4*q + 1], ac1);
        atomicAdd(&csum[4*q + 2], ac2);
        atomicAdd(&csum[4*q + 3], ac3);
        __syncthreads();

        // ---- scaled gather: sxs[jj][f] = x[b, jg*8+t, f] / colsum[jj] ----
        if (tid < SW * FF) {
            const int cc2 = tid >> 2, ff = tid & 3;
            const int jg = j0 + cc2;
            const float gx = x[((size_t)b * NN + jg * TT + t) * FF + ff];
            sxs[tid] = gx / csum[cc2];
        }
        __syncthreads();

        // ---- phase 2: acc[f] += sum_jj num[i, jj] * sxs[jj][f] ----
        const int i0 = tid, i1 = tid + NTHREADS;
        #pragma unroll
        for (int g = 0; g < 4; ++g) {
            const float4 n0 = *reinterpret_cast<const float4*>(
                &num[i0 * RSTRIDE + 4 * g]);
            const float4 n1 = *reinterpret_cast<const float4*>(
                &num[i1 * RSTRIDE + 4 * g]);
            const float nn0[4] = {n0.x, n0.y, n0.z, n0.w};
            const float nn1[4] = {n1.x, n1.y, n1.z, n1.w};
            #pragma unroll
            for (int l = 0; l < 4; ++l) {
                const float4 sx4 = *reinterpret_cast<const float4*>(
                    &sxs[(4 * g + l) * FF]);
                acc0[0] = fmaf(nn0[l], sx4.x, acc0[0]);
                acc0[1] = fmaf(nn0[l], sx4.y, acc0[1]);
                acc0[2] = fmaf(nn0[l], sx4.z, acc0[2]);
                acc0[3] = fmaf(nn0[l], sx4.w, acc0[3]);
                acc1[0] = fmaf(nn1[l], sx4.x, acc1[0]);
                acc1[1] = fmaf(nn1[l], sx4.y, acc1[1]);
                acc1[2] = fmaf(nn1[l], sx4.z, acc1[2]);
                acc1[3] = fmaf(nn1[l], sx4.w, acc1[3]);
            }
        }
        __syncthreads();
    }

    float4* p0 = reinterpret_cast<float4*>(g_partial) + ((size_t)unit * CC + tid);
    *p0 = make_float4(acc0[0], acc0[1], acc0[2], acc0[3]);
    float4* p1 = p0 + NTHREADS;
    *p1 = make_float4(acc1[0], acc1[1], acc1[2], acc1[3]);
}

// Reduce: 2 threads per output (8 partials each), shfl combine, scatter.
__global__ void reduce_scatter_kernel(float* __restrict__ out) {
    const int gid = blockIdx.x * blockDim.x + threadIdx.x;  // [0, TB*CC*2)
    const int o  = gid >> 1;
    const int h  = gid & 1;
    const int i  = o & (CC - 1);
    const int tb = o >> 10;
    const int t = tb >> 3, b = tb & 7;
    const float4* pp = reinterpret_cast<const float4*>(g_partial);
    float4 a = make_float4(0.f, 0.f, 0.f, 0.f);
    #pragma unroll
    for (int q = 0; q < 8; ++q) {
        const float4 p = pp[(size_t)(tb * JQ + h * 8 + q) * CC + i];
        a.x += p.x; a.y += p.y; a.z += p.z; a.w += p.w;
    }
    a.x += __shfl_xor_sync(0xffffffffu, a.x, 1);
    a.y += __shfl_xor_sync(0xffffffffu, a.y, 1);
    a.z += __shfl_xor_sync(0xffffffffu, a.z, 1);
    a.w += __shfl_xor_sync(0xffffffffu, a.w, 1);
    if (h == 0)
        reinterpret_cast<float4*>(out)[(size_t)b * NN + i * TT + t] = a;
}

extern "C" void kernel_launch(void* const* d_in, const int* in_sizes, int n_in,
                              void* d_out, int out_size) {
    const float* x = (const float*)d_in[0];
    const float* w = (const float*)d_in[1];
    float* out = (float*)d_out;
    (void)in_sizes; (void)n_in; (void)out_size;

    cudaFuncSetAttribute(fused_retina_kernel,
                         cudaFuncAttributeMaxDynamicSharedMemorySize, SMEM_BYTES);
    fused_retina_kernel<<<UNITS, NTHREADS, SMEM_BYTES>>>(x, w);
    reduce_scatter_kernel<<<(TB * CC * 2) / 256, 256>>>(out);
}

// round 8
// speedup vs baseline: 1.2135x; 1.2135x over previous
#include <cuda_runtime.h>
#include <stdint.h>

// B=8, T=8, C=1024, F=4, N=8192
#define TT 8
#define BB 8
#define CC 1024
#define FF 4
#define NN (TT*CC)
#define TB 64                   // (t,b) pairs
#define SW 16                   // strip width (columns staged in smem)
#define JQ 16                   // column units per (t,b)
#define UNITS (TB*JQ)           // 1024 CTAs
#define STRIPS 4                // 64 cols per unit / SW
#define NTHREADS 1024
#define KITER 16                // 1024 rows / 64 row-groups
#define NSTRIDE 1026            // EVEN stride: half-warps hit opposite bank parity
#define SMEM_BYTES ((SW*NSTRIDE + SW*FF + SW)*4)   // 65984 B -> 2 CTAs/SM

// per-unit partial results [unit][i][f] : 16 MB scratch
__device__ float g_partial[(size_t)UNITS * CC * FF];
// opaque 1 so ptxas keeps mad.lo as IMAD (fma pipe)
__device__ uint32_t g_one = 1u;

__device__ __forceinline__ uint32_t tf_rotl(uint32_t x, int d) {
    return __funnelshift_l(x, x, d);
}
__device__ __forceinline__ uint32_t addf(uint32_t a, uint32_t one, uint32_t b) {
    uint32_t d;
    asm("mad.lo.u32 %0, %1, %2, %3;" : "=r"(d) : "r"(a), "r"(one), "r"(b));
    return d;
}

// JAX threefry2x32 partitionable: key=(0,42), counter=(0,e), out = x0^x1.
// Takes y = e + 42 (key pre-injected by caller); round 1 simplified since
// x0 starts at 0: x0 = 0 + x1 = y, x1 = rotl(y,13) ^ y.
__device__ __forceinline__ uint32_t threefry_bits(uint32_t y, uint32_t one) {
    const uint32_t K1 = 42u;
    const uint32_t K2 = 0x1BD11BDAu ^ 42u;
    uint32_t x0 = y;
    uint32_t x1 = tf_rotl(y, 13) ^ y;
#define TF_R(d) { x0 = addf(x0, one, x1); x1 = tf_rotl(x1,(d)) ^ x0; }
    TF_R(15) TF_R(26) TF_R(6)
    x0 = addf(x0,one,K1); x1 = addf(x1,one,K2+1u);
    TF_R(17) TF_R(29) TF_R(16) TF_R(24)
    x0 = addf(x0,one,K2); x1 = addf(x1,one,2u);
    TF_R(13) TF_R(15) TF_R(26) TF_R(6)
                          x1 = addf(x1,one,K1+3u);
    TF_R(17) TF_R(29) TF_R(16) TF_R(24)
    x0 = addf(x0,one,K1); x1 = addf(x1,one,K2+4u);
    TF_R(13) TF_R(15) TF_R(26) TF_R(6)
    x0 = addf(x0,one,K2); x1 = addf(x1,one,5u);
#undef TF_R
    return x0 ^ x1;
}

__device__ __forceinline__ float ex2_fast(float a) {
    float r;
    asm("ex2.approx.ftz.f32 %0, %1;" : "=f"(r) : "f"(a));
    return r;
}

// One unit = (tb, jq): 64 columns x 1024 rows of one (t,b) weight matrix.
// Per strip: num = exp(w + g) up to the softmax-invariant scale, computed as
// ex2(w*log2e - log2(-ln u)). -ln u: exact v=1-u (Sterbenz) + 3-term series
// for u->1 (relative accuracy where it matters), MUFU lg2 elsewhere.
__global__ __launch_bounds__(NTHREADS, 2)
void fused_retina_kernel(const float* __restrict__ x,
                         const float* __restrict__ w) {
    const int unit = blockIdx.x;
    const int tb = unit >> 4;
    const int jq = unit & (JQ - 1);
    const int t  = tb >> 3;
    const int b  = tb & 7;
    const int jbase = jq * (STRIPS * SW);

    extern __shared__ float smem[];
    float* num  = smem;                     // [SW][NSTRIDE]
    float* sxs  = num + SW * NSTRIDE;       // [SW][FF], 16B aligned
    float* csum = sxs + SW * FF;            // [SW]

    const int tid = threadIdx.x;
    const int c   = tid & (SW - 1);         // column within strip
    const int r   = tid >> 4;               // 0..63 row group
    const uint32_t one = g_one;

    float acc[FF] = {0.f, 0.f, 0.f, 0.f};   // row i = tid
    const uint32_t ebase = ((uint32_t)tb << 20);

    for (int s = 0; s < STRIPS; ++s) {
        const int j0 = jbase + s * SW;
        if (tid < SW) csum[tid] = 0.f;
        __syncthreads();

        // ---- phase 1: hash + numerator + column partial sums ----
        const int j = j0 + c;
        const float* wcol = w + ((size_t)tb << 20) + ((size_t)r << 10) + j;
        // counter with key pre-injected: y = e + 42
        const uint32_t y0 = (ebase | ((uint32_t)r << 10) | (uint32_t)j) + 42u;
        float part = 0.f;
        #pragma unroll 4
        for (int k = 0; k < KITER; ++k) {
            const int i = (k << 6) + r;
            const float ww = __ldg(wcol + ((size_t)k << 16));
            const uint32_t bits = threefry_bits(y0 + ((uint32_t)k << 16), one);
            // (bits>>9)|0x3f800000 as IMAD.HI + IADD (exact, disjoint bits)
            const uint32_t ub = __umulhi(bits, 1u << 23) + 0x3f800000u;
            const float f = __uint_as_float(ub) - 1.0f;
            const float u = fmaxf(f, 1.17549435e-38f);
            // -ln u: exact series near u=1, else lg2(u) * -ln2
            const float v = 1.0f - u;
            const float poly = fmaf(v * v, fmaf(v, 0.33333333f, 0.5f), v);
            const float l2u = __log2f(u);
            const float p = (v <= 0.015625f) ? poly : (l2u * -0.69314718f);
            // nv = 2^(w*log2e - log2(p)) = exp(w)/(-ln u)
            const float nv = ex2_fast(fmaf(ww, 1.44269504f, -__log2f(p)));
            num[c * NSTRIDE + i] = nv;
            part += nv;
        }
        // lanes l and l^16 share a column: pre-reduce, then 16 atomics/warp
        part += __shfl_xor_sync(0xffffffffu, part, 16);
        if ((tid & 31) < SW) atomicAdd(&csum[c], part);
        __syncthreads();

        // ---- scaled gather: sxs[jj][f] = x[b, jg*8+t, f] / colsum[jj] ----
        if (tid < SW * FF) {
            const int cc2 = tid >> 2, ff = tid & 3;
            const int jg = j0 + cc2;
            const float gx = x[((size_t)b * NN + jg * TT + t) * FF + ff];
            sxs[tid] = gx / csum[cc2];
        }
        __syncthreads();

        // ---- phase 2: acc[f] += sum_jj num[tid, jj] * sxs[jj][f] ----
        #pragma unroll
        for (int jj = 0; jj < SW; ++jj) {
            const float4 sx4 = *reinterpret_cast<const float4*>(&sxs[jj * FF]);
            const float nv = num[jj * NSTRIDE + tid];
            acc[0] = fmaf(nv, sx4.x, acc[0]);
            acc[1] = fmaf(nv, sx4.y, acc[1]);
            acc[2] = fmaf(nv, sx4.z, acc[2]);
            acc[3] = fmaf(nv, sx4.w, acc[3]);
        }
        __syncthreads();
    }

    float4* p = reinterpret_cast<float4*>(g_partial) + ((size_t)unit * CC + tid);
    *p = make_float4(acc[0], acc[1], acc[2], acc[3]);
}

// Reduce: 2 threads per output (8 partials each), shfl combine, scatter.
__global__ void reduce_scatter_kernel(float* __restrict__ out) {
    const int gid = blockIdx.x * blockDim.x + threadIdx.x;  // [0, TB*CC*2)
    const int o  = gid >> 1;
    const int h  = gid & 1;
    const int i  = o & (CC - 1);
    const int tb = o >> 10;
    const int t = tb >> 3, b = tb & 7;
    const float4* pp = reinterpret_cast<const float4*>(g_partial);
    float4 a = make_float4(0.f, 0.f, 0.f, 0.f);
    #pragma unroll
    for (int q = 0; q < 8; ++q) {
        const float4 p = pp[(size_t)(tb * JQ + h * 8 + q) * CC + i];
        a.x += p.x; a.y += p.y; a.z += p.z; a.w += p.w;
    }
    a.x += __shfl_xor_sync(0xffffffffu, a.x, 1);
    a.y += __shfl_xor_sync(0xffffffffu, a.y, 1);
    a.z += __shfl_xor_sync(0xffffffffu, a.z, 1);
    a.w += __shfl_xor_sync(0xffffffffu, a.w, 1);
    if (h == 0)
        reinterpret_cast<float4*>(out)[(size_t)b * NN + i * TT + t] = a;
}

extern "C" void kernel_launch(void* const* d_in, const int* in_sizes, int n_in,
                              void* d_out, int out_size) {
    const float* x = (const float*)d_in[0];
    const float* w = (const float*)d_in[1];
    float* out = (float*)d_out;
    (void)in_sizes; (void)n_in; (void)out_size;

    cudaFuncSetAttribute(fused_retina_kernel,
                         cudaFuncAttributeMaxDynamicSharedMemorySize, SMEM_BYTES);
    fused_retina_kernel<<<UNITS, NTHREADS, SMEM_BYTES>>>(x, w);
    reduce_scatter_kernel<<<(TB * CC * 2) / 256, 256>>>(out);
}

// round 9
// speedup vs baseline: 1.2554x; 1.0345x over previous
#include <cuda_runtime.h>
#include <stdint.h>

// B=8, T=8, C=1024, F=4, N=8192
#define TT 8
#define BB 8
#define CC 1024
#define FF 4
#define NN (TT*CC)
#define TB 64                   // (t,b) pairs
#define SW 16                   // strip width (columns staged in smem)
#define JQ 16                   // column units per (t,b)
#define UNITS (TB*JQ)           // 1024 CTAs
#define STRIPS 4                // 64 cols per unit / SW
#define NTHREADS 1024
#define KITER 16                // 1024 rows / 64 row-groups
#define NSTRIDE 1026            // EVEN stride: half-warps hit opposite bank parity
#define SMEM_BYTES ((SW*NSTRIDE + SW*FF + SW)*4)   // 65984 B -> 2 CTAs/SM

// per-unit partial results [unit][i][f] : 16 MB scratch
__device__ float g_partial[(size_t)UNITS * CC * FF];

__device__ __forceinline__ uint32_t tf_rotl(uint32_t x, int d) {
    return __funnelshift_l(x, x, d);
}

// JAX threefry2x32 partitionable: key=(0,42), counter=(0,e), out = x0^x1.
// Takes y = e + 42 (key pre-injected by caller). Round 1 simplified (x0
// starts at 0). Key-schedule injections written so the x0-injection fuses
// with the next round-add into one IADD3 (x0 = x0 + x1 + K).
__device__ __forceinline__ uint32_t threefry_bits(uint32_t y) {
    const uint32_t K1 = 42u;
    const uint32_t K2 = 0x1BD11BDAu ^ 42u;
    uint32_t x0 = y;
    uint32_t x1 = tf_rotl(y, 13) ^ y;
#define TF_R(d) { x0 += x1; x1 = tf_rotl(x1,(d)) ^ x0; }
    TF_R(15) TF_R(26) TF_R(6)
    // block boundary 1: x0 += K1; x1 += K2+1; then round(17)
    x1 += K2 + 1u;
    x0 += x1 + K1;                       // IADD3 fusion
    x1 = tf_rotl(x1, 17) ^ x0;
    TF_R(29) TF_R(16) TF_R(24)
    // boundary 2: x0 += K2; x1 += 2
    x1 += 2u;
    x0 += x1 + K2;                       // IADD3 fusion
    x1 = tf_rotl(x1, 13) ^ x0;
    TF_R(15) TF_R(26) TF_R(6)
    // boundary 3: x0 += 0; x1 += K1+3
    x1 += K1 + 3u;
    x0 += x1;
    x1 = tf_rotl(x1, 17) ^ x0;
    TF_R(29) TF_R(16) TF_R(24)
    // boundary 4: x0 += K1; x1 += K2+4
    x1 += K2 + 4u;
    x0 += x1 + K1;                       // IADD3 fusion
    x1 = tf_rotl(x1, 13) ^ x0;
    TF_R(15) TF_R(26) TF_R(6)
    // final injection: x0 += K2; x1 += 5
    return (x0 + K2) ^ (x1 + 5u);
#undef TF_R
}

__device__ __forceinline__ float ex2_fast(float a) {
    float r;
    asm("ex2.approx.ftz.f32 %0, %1;" : "=f"(r) : "f"(a));
    return r;
}
__device__ __forceinline__ unsigned long long pack2(float v) {
    unsigned long long d;
    const uint32_t r = __float_as_uint(v);
    asm("mov.b64 %0, {%1, %1};" : "=l"(d) : "r"(r));
    return d;
}
__device__ __forceinline__ void ffma2(unsigned long long& acc,
                                      unsigned long long a,
                                      unsigned long long b) {
    asm("fma.rn.f32x2 %0, %1, %2, %0;" : "+l"(acc) : "l"(a), "l"(b));
}

// One unit = (tb, jq): 64 columns x 1024 rows of one (t,b) weight matrix.
// Per strip: num = exp(w + g) up to the softmax-invariant scale, computed as
// ex2(w*log2e - log2(-ln u)). -ln u: exact v=1-u (Sterbenz) + 3-term series
// for u->1 (relative accuracy where it matters), MUFU lg2 elsewhere.
__global__ __launch_bounds__(NTHREADS, 2)
void fused_retina_kernel(const float* __restrict__ x,
                         const float* __restrict__ w) {
    const int unit = blockIdx.x;
    const int tb = unit >> 4;
    const int jq = unit & (JQ - 1);
    const int t  = tb >> 3;
    const int b  = tb & 7;
    const int jbase = jq * (STRIPS * SW);

    extern __shared__ float smem[];
    float* num  = smem;                     // [SW][NSTRIDE]
    float* sxs  = num + SW * NSTRIDE;       // [SW][FF], 16B aligned
    float* csum = sxs + SW * FF;            // [SW]

    const int tid = threadIdx.x;
    const int c   = tid & (SW - 1);         // column within strip
    const int r   = tid >> 4;               // 0..63 row group

    unsigned long long acc01 = 0ull, acc23 = 0ull;  // packed f32x2 accum
    const uint32_t ebase = ((uint32_t)tb << 20);

    for (int s = 0; s < STRIPS; ++s) {
        const int j0 = jbase + s * SW;
        if (tid < SW) csum[tid] = 0.f;
        __syncthreads();

        // ---- phase 1: hash + numerator + column partial sums ----
        const int j = j0 + c;
        const float* wcol = w + ((size_t)tb << 20) + ((size_t)r << 10) + j;
        // counter with key pre-injected: y = e + 42
        const uint32_t y0 = (ebase | ((uint32_t)r << 10) | (uint32_t)j) + 42u;
        float part = 0.f;
        #pragma unroll 4
        for (int k = 0; k < KITER; ++k) {
            const int i = (k << 6) + r;
            const float ww = __ldg(wcol + ((size_t)k << 16));
            const uint32_t bits = threefry_bits(y0 + ((uint32_t)k << 16));
            // (bits>>9)|0x3f800000 as IMAD.HI + IADD (exact, disjoint bits)
            const uint32_t ub = __umulhi(bits, 1u << 23) + 0x3f800000u;
            const float f = __uint_as_float(ub) - 1.0f;
            const float u = fmaxf(f, 1.17549435e-38f);
            // -ln u: exact series near u=1, else lg2(u) * -ln2
            const float v = 1.0f - u;
            const float poly = fmaf(v * v, fmaf(v, 0.33333333f, 0.5f), v);
            const float l2u = __log2f(u);
            const float p = (v <= 0.015625f) ? poly : (l2u * -0.69314718f);
            // nv = 2^(w*log2e - log2(p)) = exp(w)/(-ln u)
            const float nv = ex2_fast(fmaf(ww, 1.44269504f, -__log2f(p)));
            num[c * NSTRIDE + i] = nv;
            part += nv;
        }
        // lanes l and l^16 share a column: pre-reduce, then 16 atomics/warp
        part += __shfl_xor_sync(0xffffffffu, part, 16);
        if ((tid & 31) < SW) atomicAdd(&csum[c], part);
        __syncthreads();

        // ---- scaled gather: sxs[jj][f] = x[b, jg*8+t, f] / colsum[jj] ----
        if (tid < SW * FF) {
            const int cc2 = tid >> 2, ff = tid & 3;
            const int jg = j0 + cc2;
            const float gx = x[((size_t)b * NN + jg * TT + t) * FF + ff];
            sxs[tid] = gx / csum[cc2];
        }
        __syncthreads();

        // ---- phase 2: acc[f] += sum_jj num[tid, jj] * sxs[jj][f] ----
        #pragma unroll
        for (int jj = 0; jj < SW; ++jj) {
            const ulonglong2 s2 =
                *reinterpret_cast<const ulonglong2*>(&sxs[jj * FF]);
            const unsigned long long nvp = pack2(num[jj * NSTRIDE + tid]);
            ffma2(acc01, nvp, s2.x);
            ffma2(acc23, nvp, s2.y);
        }
        __syncthreads();
    }

    ulonglong2* p = reinterpret_cast<ulonglong2*>(g_partial) +
                    ((size_t)unit * CC + tid);
    *p = make_ulonglong2(acc01, acc23);
}

// Reduce: 2 threads per output (8 partials each), shfl combine, scatter.
__global__ void reduce_scatter_kernel(float* __restrict__ out) {
    const int gid = blockIdx.x * blockDim.x + threadIdx.x;  // [0, TB*CC*2)
    const int o  = gid >> 1;
    const int h  = gid & 1;
    const int i  = o & (CC - 1);
    const int tb = o >> 10;
    const int t = tb >> 3, b = tb & 7;
    const float4* pp = reinterpret_cast<const float4*>(g_partial);
    float4 a = make_float4(0.f, 0.f, 0.f, 0.f);
    #pragma unroll
    for (int q = 0; q < 8; ++q) {
        const float4 p = pp[(size_t)(tb * JQ + h * 8 + q) * CC + i];
        a.x += p.x; a.y += p.y; a.z += p.z; a.w += p.w;
    }
    a.x += __shfl_xor_sync(0xffffffffu, a.x, 1);
    a.y += __shfl_xor_sync(0xffffffffu, a.y, 1);
    a.z += __shfl_xor_sync(0xffffffffu, a.z, 1);
    a.w += __shfl_xor_sync(0xffffffffu, a.w, 1);
    if (h == 0)
        reinterpret_cast<float4*>(out)[(size_t)b * NN + i * TT + t] = a;
}

extern "C" void kernel_launch(void* const* d_in, const int* in_sizes, int n_in,
                              void* d_out, int out_size) {
    const float* x = (const float*)d_in[0];
    const float* w = (const float*)d_in[1];
    float* out = (float*)d_out;
    (void)in_sizes; (void)n_in; (void)out_size;

    cudaFuncSetAttribute(fused_retina_kernel,
                         cudaFuncAttributeMaxDynamicSharedMemorySize, SMEM_BYTES);
    fused_retina_kernel<<<UNITS, NTHREADS, SMEM_BYTES>>>(x, w);
    reduce_scatter_kernel<<<(TB * CC * 2) / 256, 256>>>(out);
}